// round 1
// baseline (speedup 1.0000x reference)
#include <cuda_runtime.h>
#include <cstdint>

// StreamingSTFT collapses analytically:
//   irfft(rfft(x)) == x  =>  frame = in_buf * aw * sw
//   sw nonzero only on [96,160)  =>  overlap-add reduces to
//   out[i][j] = chunk[i-3][j] * W[j]   (i >= 3), else 0
//   W[j] = aw[j+128]*sw[j+128] (j<32) ; aw[j+64]*sw[j+64] (j>=32)
//
// Pure streaming elementwise kernel: 32 MB in + 32 MB out. HBM-bound.

static constexpr int HOP = 64;
static constexpr long long NUM_FRAMES = 131072;
static constexpr long long N_ELEMS = NUM_FRAMES * HOP;   // 8,388,608
static constexpr long long N_VEC4  = N_ELEMS / 4;        // 2,097,152
static constexpr int DELAY_VEC4 = (3 * HOP) / 4;         // 48 float4s = 3 rows

__global__ void __launch_bounds__(256)
stft_delay_scale_kernel(const float4* __restrict__ chunk4,
                        const float*  __restrict__ aw,
                        const float*  __restrict__ sw,
                        float4* __restrict__ out4)
{
    long long i = (long long)blockIdx.x * blockDim.x + threadIdx.x;
    if (i >= N_VEC4) return;

    // j0 = starting column of this float4 within the 64-wide row (16 float4/row)
    int j0 = ((int)(i & 15)) << 2;
    // Window base index: all 4 lanes of the float4 fall on the same branch
    // (j0 is a multiple of 4, so j0<32 <=> j0+3<32).
    int base = j0 + (j0 < 32 ? 128 : 64);       // multiple of 4 -> float4 aligned

    const float4 a = *reinterpret_cast<const float4*>(aw + base);
    const float4 s = *reinterpret_cast<const float4*>(sw + base);

    float4 v;
    if (i >= DELAY_VEC4) {
        v = __ldg(chunk4 + (i - DELAY_VEC4));
    } else {
        v = make_float4(0.f, 0.f, 0.f, 0.f);
    }

    float4 o;
    o.x = v.x * a.x * s.x;
    o.y = v.y * a.y * s.y;
    o.z = v.z * a.z * s.z;
    o.w = v.w * a.w * s.w;
    out4[i] = o;
}

extern "C" void kernel_launch(void* const* d_in, const int* in_sizes, int n_in,
                              void* d_out, int out_size)
{
    const float4* chunk4 = reinterpret_cast<const float4*>(d_in[0]);
    const float*  aw     = reinterpret_cast<const float*>(d_in[1]);
    const float*  sw     = reinterpret_cast<const float*>(d_in[2]);
    float4*       out4   = reinterpret_cast<float4*>(d_out);

    const int threads = 256;
    const int blocks  = (int)((N_VEC4 + threads - 1) / threads);  // 8192
    stft_delay_scale_kernel<<<blocks, threads>>>(chunk4, aw, sw, out4);
}

// round 2
// speedup vs baseline: 1.0533x; 1.0533x over previous
#include <cuda_runtime.h>
#include <cstdint>

// StreamingSTFT collapses analytically:
//   irfft(rfft(x)) == x  =>  frame = in_buf * aw * sw
//   sw nonzero only on [96,160)  =>  overlap-add reduces to
//   out[i][j] = chunk[i-3][j] * W[j]   (i >= 3), else 0
//   W[j] = aw[j+128]*sw[j+128] (j<32) ; aw[j+64]*sw[j+64] (j>=32)
//
// R1: single-wave launch (1024 blocks ~= 7/SM), 8 float4 per thread with
// full unroll -> MLP=8 front-batched loads; window product hoisted out of
// the loop (stride divisible by 16 keeps the lane's column fixed).

static constexpr int HOP = 64;
static constexpr long long NUM_FRAMES = 131072;
static constexpr long long N_ELEMS = NUM_FRAMES * HOP;   // 8,388,608
static constexpr long long N_VEC4  = N_ELEMS / 4;        // 2,097,152
static constexpr int DELAY_VEC4 = (3 * HOP) / 4;         // 48 float4s = 3 rows

static constexpr int BLOCKS  = 1024;
static constexpr int THREADS = 256;
static constexpr int STRIDE  = BLOCKS * THREADS;         // 262144, %16 == 0
static constexpr int ITERS   = (int)(N_VEC4 / STRIDE);   // exactly 8

__global__ void __launch_bounds__(THREADS)
stft_delay_scale_kernel(const float4* __restrict__ chunk4,
                        const float*  __restrict__ aw,
                        const float*  __restrict__ sw,
                        float4* __restrict__ out4)
{
    const int i0 = blockIdx.x * THREADS + threadIdx.x;

    // Column of this lane within the 64-wide row; invariant across the
    // strided loop because STRIDE % 16 == 0.
    const int j0   = (i0 & 15) << 2;
    const int base = j0 + (j0 < 32 ? 128 : 64);           // float4-aligned

    const float4 a = *reinterpret_cast<const float4*>(aw + base);
    const float4 s = *reinterpret_cast<const float4*>(sw + base);
    const float4 w = make_float4(a.x * s.x, a.y * s.y, a.z * s.z, a.w * s.w);

    // Front-batch all 8 loads (independent -> MLP = 8).
    float4 v[ITERS];
#pragma unroll
    for (int k = 0; k < ITERS; k++) {
        const long long i = (long long)i0 + (long long)k * STRIDE;
        if (i >= DELAY_VEC4) {
            v[k] = __ldg(chunk4 + (i - DELAY_VEC4));
        } else {
            v[k] = make_float4(0.f, 0.f, 0.f, 0.f);
        }
    }

#pragma unroll
    for (int k = 0; k < ITERS; k++) {
        const long long i = (long long)i0 + (long long)k * STRIDE;
        float4 o;
        o.x = v[k].x * w.x;
        o.y = v[k].y * w.y;
        o.z = v[k].z * w.z;
        o.w = v[k].w * w.w;
        out4[i] = o;
    }
}

extern "C" void kernel_launch(void* const* d_in, const int* in_sizes, int n_in,
                              void* d_out, int out_size)
{
    const float4* chunk4 = reinterpret_cast<const float4*>(d_in[0]);
    const float*  aw     = reinterpret_cast<const float*>(d_in[1]);
    const float*  sw     = reinterpret_cast<const float*>(d_in[2]);
    float4*       out4   = reinterpret_cast<float4*>(d_out);

    stft_delay_scale_kernel<<<BLOCKS, THREADS>>>(chunk4, aw, sw, out4);
}